// round 14
// baseline (speedup 1.0000x reference)
#include <cuda_runtime.h>
#include <cuda_fp16.h>
#include <cstdint>

#define BB 8
#define C 256
#define G 16
#define KK 9
#define GKK 144
#define HW 4096
#define IMG_W 64
#define IMG_H 64

typedef unsigned long long u64;
typedef unsigned int u32;

__device__ __align__(16) __half g_kmaph[BB * GKK * HW];   // 9.4 MB fp16 scratch

// ---------- scalar helpers ----------
__device__ __forceinline__ u64 ffma2(u64 a, u64 b, u64 c) {
    u64 d; asm("fma.rn.f32x2 %0, %1, %2, %3;" : "=l"(d) : "l"(a), "l"(b), "l"(c)); return d;
}
__device__ __forceinline__ u64 pk(float lo, float hi) {
    u64 r; asm("mov.b64 %0, {%1, %2};" : "=l"(r) : "f"(lo), "f"(hi)); return r;
}
__device__ __forceinline__ float lo32(u64 v) { return __uint_as_float((u32)v); }
__device__ __forceinline__ float hi32(u64 v) { return __uint_as_float((u32)(v >> 32)); }

__device__ __forceinline__ u32 h2u(__half2 h) { u32 r; memcpy(&r, &h, 4); return r; }
__device__ __forceinline__ void split2h(float v0, float v1, u32& h2, u32& l2) {
    __half2 h = __floats2half2_rn(v0, v1);
    h2 = h2u(h);
    l2 = h2u(__floats2half2_rn(v0 - __low2float(h), v1 - __high2float(h)));
}
__device__ __forceinline__ void cvt4h(float4 v, u64& h, u64& l) {
    u32 h0, l0, h1, l1;
    split2h(v.x, v.y, h0, l0);
    split2h(v.z, v.w, h1, l1);
    h = (u64)h0 | ((u64)h1 << 32);
    l = (u64)l0 | ((u64)l1 << 32);
}
__device__ __forceinline__ u64 cvt4h1(float4 v) {
    u32 a = h2u(__floats2half2_rn(v.x, v.y));
    u32 b = h2u(__floats2half2_rn(v.z, v.w));
    return (u64)a | ((u64)b << 32);
}
__device__ __forceinline__ u32 smem_u32(const void* p) {
    u32 a; asm("{ .reg .u64 t; cvta.to.shared.u64 t, %1; cvt.u32.u64 %0, t; }" : "=r"(a) : "l"(p));
    return a;
}

#define MMA(d, a, b0, b1) \
    asm volatile("mma.sync.aligned.m16n8k16.row.col.f32.f16.f16.f32 " \
        "{%0,%1,%2,%3}, {%4,%5,%6,%7}, {%8,%9}, {%0,%1,%2,%3};" \
        : "+f"((d)[0]), "+f"((d)[1]), "+f"((d)[2]), "+f"((d)[3]) \
        : "r"((a)[0]), "r"((a)[1]), "r"((a)[2]), "r"((a)[3]), "r"(b0), "r"(b1))

#define LDSM4T(r, addr) \
    asm volatile("ldmatrix.sync.aligned.m8n8.x4.trans.shared.b16 {%0,%1,%2,%3}, [%4];" \
        : "=r"((r)[0]), "=r"((r)[1]), "=r"((r)[2]), "=r"((r)[3]) : "r"(addr))

#define LDSM4(r, addr) \
    asm volatile("ldmatrix.sync.aligned.m8n8.x4.shared.b16 {%0,%1,%2,%3}, [%4];" \
        : "=r"((r)[0]), "=r"((r)[1]), "=r"((r)[2]), "=r"((r)[3]) : "r"(addr))

// smem byte layout (k_gemm); region [0,43008) reused for kmap staging (39168B)
#define OFF_XH   0
#define OFF_XL   16384
#define OFF_W1H  32768
#define OFF_WSPH 43008
#define SM_TOTAL 63744
#define KROW 272          // staging row stride bytes (17*16; o-step 2 -> +8 banks)

// ---------------------------------------------------------------------------
// k_gemm: fp16 2-product HMMA GEMMs; kmap staged to smem as fp16, then
// coalesced STG.128 to g_kmaph.
// ---------------------------------------------------------------------------
__global__ __launch_bounds__(256, 2)
void k_gemm(const float* __restrict__ x, const float* __restrict__ wr,
            const float* __restrict__ br, const float* __restrict__ wsp,
            const float* __restrict__ bs) {
    extern __shared__ __align__(16) char smem[];
    const int tid = threadIdx.x, wid = tid >> 5, lane = tid & 31;
    const int b = blockIdx.x >> 5, pt = (blockIdx.x & 31) << 7;
    const u32 sbase = smem_u32(smem);

#pragma unroll
    for (int i = 0; i < 9; i++) {
        int f4 = tid + i * 256;
        float4 v = *(const float4*)(wsp + f4 * 4);
        int n = f4 >> 4, kc = (f4 & 15) * 4;
        *(u64*)(smem + OFF_WSPH + n * 144 + kc * 2) = cvt4h1(v);
    }
    {
        const int c = tid >> 3, pxb = (tid & 7) * 16;
        const float* xsrc = x + ((size_t)(b * C + c)) * HW + pt + pxb;
        const int csw = (c & 7) << 3;
#pragma unroll
        for (int q = 0; q < 4; q++) {
            float4 v = *(const float4*)(xsrc + q * 4);
            int col = (pxb + q * 4) ^ csw;
            u64 h, l;
            cvt4h(v, h, l);
            *(u64*)(smem + OFF_XH + c * 256 + col * 2) = h;
            *(u64*)(smem + OFF_XL + c * 256 + col * 2) = l;
        }
        const int n = tid >> 2, koff = (tid & 3) * 8;
#pragma unroll
        for (int q = 0; q < 2; q++) {
            float4 v = *(const float4*)(wr + n * C + koff + q * 4);
            *(u64*)(smem + OFF_W1H + n * 80 + (koff + q * 4) * 2) = cvt4h1(v);
        }
    }
    __syncthreads();

    float acc1[8][4];
#pragma unroll
    for (int j = 0; j < 8; j++)
#pragma unroll
        for (int q = 0; q < 4; q++) acc1[j][q] = 0.f;

    const int m0 = wid * 16;
    const int grp = lane >> 3, li = lane & 7;
    const int krow_off = ((grp & 2) << 2) + li;
    const int coladd = (grp & 1) << 3;
    const int brow = ((lane >> 4) << 3) + li;
    const int bkadd = (grp & 1) << 3;

#pragma unroll 1
    for (int ck = 0; ck < 8; ck++) {
        const int cur = ck & 1, nxt = cur ^ 1;
        float4 xr[4], wrr[2];
        if (ck < 7) {
            const int c = tid >> 3, pxb = (tid & 7) * 16;
            const float* xsrc = x + ((size_t)(b * C + (ck + 1) * 32 + c)) * HW + pt + pxb;
#pragma unroll
            for (int q = 0; q < 4; q++) xr[q] = *(const float4*)(xsrc + q * 4);
            const int n = tid >> 2, koff = (tid & 3) * 8;
#pragma unroll
            for (int q = 0; q < 2; q++)
                wrr[q] = *(const float4*)(wr + n * C + (ck + 1) * 32 + koff + q * 4);
        }
        const u32 sxh = sbase + OFF_XH + cur * 8192;
        const u32 sw1h = sbase + OFF_W1H + cur * 5120;

#pragma unroll
        for (int ks = 0; ks < 2; ks++) {
            const int kb = ks * 16;
            u32 AH[4], AL[4];
            {
                int col = (m0 + coladd) ^ (li << 3);
                u32 ah = sxh + (u32)((kb + krow_off) * 256 + col * 2);
                LDSM4T(AH, ah);
                LDSM4T(AL, ah + 16384);
            }
#pragma unroll
            for (int nj2 = 0; nj2 < 4; nj2++) {
                u32 boff = (u32)((nj2 * 16 + brow) * 80 + (kb + bkadd) * 2);
                u32 BH[4];
                LDSM4(BH, sw1h + boff);
                MMA(acc1[2 * nj2], AH, BH[0], BH[1]);
                MMA(acc1[2 * nj2], AL, BH[0], BH[1]);
                MMA(acc1[2 * nj2 + 1], AH, BH[2], BH[3]);
                MMA(acc1[2 * nj2 + 1], AL, BH[2], BH[3]);
            }
        }
        if (ck < 7) {
            const int c = tid >> 3, pxb = (tid & 7) * 16;
            const int csw = (c & 7) << 3;
#pragma unroll
            for (int q = 0; q < 4; q++) {
                int col = (pxb + q * 4) ^ csw;
                u64 h, l;
                cvt4h(xr[q], h, l);
                *(u64*)(smem + OFF_XH + nxt * 8192 + c * 256 + col * 2) = h;
                *(u64*)(smem + OFF_XL + nxt * 8192 + c * 256 + col * 2) = l;
            }
            const int n = tid >> 2, koff = (tid & 3) * 8;
#pragma unroll
            for (int q = 0; q < 2; q++)
                *(u64*)(smem + OFF_W1H + nxt * 5120 + n * 80 + (koff + q * 4) * 2) = cvt4h1(wrr[q]);
        }
        __syncthreads();
    }

    // ---- in-register: bias+relu+split -> stage-2 A fragments (fp16) ----
    u32 A2H[4][4], A2L[4][4];
#pragma unroll
    for (int ks = 0; ks < 4; ks++) {
        int o0 = ks * 16 + (lane & 3) * 2;
        float b0 = __ldg(br + o0),     b1 = __ldg(br + o0 + 1);
        float b8 = __ldg(br + o0 + 8), b9 = __ldg(br + o0 + 9);
        const float* t0 = acc1[2 * ks];
        const float* t1 = acc1[2 * ks + 1];
        float v0 = fmaxf(t0[0] + b0, 0.f), v1 = fmaxf(t0[1] + b1, 0.f);
        float v2 = fmaxf(t0[2] + b0, 0.f), v3 = fmaxf(t0[3] + b1, 0.f);
        float w0 = fmaxf(t1[0] + b8, 0.f), w1 = fmaxf(t1[1] + b9, 0.f);
        float w2 = fmaxf(t1[2] + b8, 0.f), w3 = fmaxf(t1[3] + b9, 0.f);
        split2h(v0, v1, A2H[ks][0], A2L[ks][0]);
        split2h(v2, v3, A2H[ks][1], A2L[ks][1]);
        split2h(w0, w1, A2H[ks][2], A2L[ks][2]);
        split2h(w2, w3, A2H[ks][3], A2L[ks][3]);
    }

    // ---- stage 2: MMA + stage kmap halves into smem [o][KROW] ----
    const u32 swsph = sbase + OFF_WSPH;
    const int pxl = wid * 16 + (lane >> 2);
#pragma unroll 1
    for (int nj2 = 0; nj2 < 9; nj2++) {
        float a2e[4] = {0.f, 0.f, 0.f, 0.f};
        float a2o[4] = {0.f, 0.f, 0.f, 0.f};
#pragma unroll
        for (int ks = 0; ks < 4; ks++) {
            u32 boff = (u32)((nj2 * 16 + brow) * 144 + (ks * 16 + bkadd) * 2);
            u32 BH[4];
            LDSM4(BH, swsph + boff);
            MMA(a2e, A2H[ks], BH[0], BH[1]);
            MMA(a2e, A2L[ks], BH[0], BH[1]);
            MMA(a2o, A2H[ks], BH[2], BH[3]);
            MMA(a2o, A2L[ks], BH[2], BH[3]);
        }
#pragma unroll
        for (int half = 0; half < 2; half++) {
            const float* a2 = half ? a2o : a2e;
            int o0 = (nj2 * 2 + half) * 8 + (lane & 3) * 2;
            float c0 = __ldg(bs + o0), c1 = __ldg(bs + o0 + 1);
            *(__half*)(smem + o0 * KROW + pxl * 2)             = __float2half_rn(a2[0] + c0);
            *(__half*)(smem + (o0 + 1) * KROW + pxl * 2)       = __float2half_rn(a2[1] + c1);
            *(__half*)(smem + o0 * KROW + (pxl + 8) * 2)       = __float2half_rn(a2[2] + c0);
            *(__half*)(smem + (o0 + 1) * KROW + (pxl + 8) * 2) = __float2half_rn(a2[3] + c1);
        }
    }
    __syncthreads();

    // ---- cooperative coalesced store: 144 o-rows x 256B ----
#pragma unroll
    for (int j = 0; j < 9; j++) {
        int lin = tid + j * 256;            // 2304 uint4 total
        int o = lin >> 4, seg = lin & 15;
        uint4 v = *(const uint4*)(smem + o * KROW + seg * 16);
        *(uint4*)(&g_kmaph[((size_t)(b * GKK + o)) * HW + pt + seg * 8]) = v;
    }
}

// ---------------------------------------------------------------------------
// k_invol: planar smem + shuffle halo; kmap read as fp16 (LDG.64).
// ---------------------------------------------------------------------------
__global__ __launch_bounds__(256, 4) void k_invol(const float* __restrict__ x,
                                                  float* __restrict__ out) {
    __shared__ __align__(16) float sm[16 * 10 * 64];   // 40 KB planar
    const int tid = threadIdx.x, strip = blockIdx.x, g = blockIdx.y, b = blockIdx.z;
    const int chbase = g * 16;
    const int cph = tid >> 7;
    const int rr  = (tid >> 4) & 7;
    const int t4  = tid & 15;
    const int R0  = strip * 8 + rr, X0 = t4 * 4;

    // kmap loads (fp16, 4 px per u64), issued first
    const __half* kb = g_kmaph + ((size_t)(b * G + g)) * KK * HW + R0 * IMG_W + X0;
    u64 kraw[9];
#pragma unroll
    for (int k = 0; k < 9; k++) kraw[k] = *(const u64*)(kb + (size_t)k * HW);

    // halo load: 16 ch x 10 rows x 64 cols, planar, coalesced
#pragma unroll
    for (int it = 0; it < 10; it++) {
        int lin = tid + it * 256;
        int ch = lin / 160;
        int rem = lin - ch * 160;
        int r = rem >> 4, c4 = rem & 15;
        int R = strip * 8 + r - 1;
        float4 v = make_float4(0.f, 0.f, 0.f, 0.f);
        if ((unsigned)R < (unsigned)IMG_H)
            v = *(const float4*)(x + ((size_t)(b * C + chbase + ch)) * HW + R * IMG_W + c4 * 4);
        *(float4*)&sm[ch * 640 + r * 64 + c4 * 4] = v;
    }

    // convert kmap halves -> packed fp32 pairs
    u64 kxy[9], kzw[9];
#pragma unroll
    for (int k = 0; k < 9; k++) {
        u32 plo = (u32)kraw[k], phi = (u32)(kraw[k] >> 32);
        float2 f01 = __half22float2(*(__half2*)&plo);
        float2 f23 = __half22float2(*(__half2*)&phi);
        kxy[k] = pk(f01.x, f01.y);
        kzw[k] = pk(f23.x, f23.y);
    }
    __syncthreads();

#pragma unroll
    for (int ci = 0; ci < 8; ci++) {
        const int ch = cph * 8 + ci;
        const float* pl = &sm[ch * 640 + rr * 64 + X0];
        u64 acc0 = 0ull, acc1 = 0ull;
#pragma unroll
        for (int dy = 0; dy < 3; dy++) {
            ulonglong2 q = *(const ulonglong2*)(pl + dy * 64);
            float a0 = lo32(q.x), a1 = hi32(q.x), a2 = lo32(q.y), a3 = hi32(q.y);
            float s  = __shfl_up_sync(0xFFFFFFFFu, a3, 1, 16);
            float b0 = __shfl_down_sync(0xFFFFFFFFu, a0, 1, 16);
            if (t4 == 0)  s  = 0.f;
            if (t4 == 15) b0 = 0.f;
            u64 pm  = pk(s,  a0);
            u64 p12 = pk(a1, a2);
            u64 p34 = pk(a3, b0);
            acc0 = ffma2(pm,  kxy[dy * 3 + 0], acc0);
            acc0 = ffma2(q.x, kxy[dy * 3 + 1], acc0);
            acc0 = ffma2(p12, kxy[dy * 3 + 2], acc0);
            acc1 = ffma2(p12, kzw[dy * 3 + 0], acc1);
            acc1 = ffma2(q.y, kzw[dy * 3 + 1], acc1);
            acc1 = ffma2(p34, kzw[dy * 3 + 2], acc1);
        }
        float4 r4;
        r4.x = lo32(acc0); r4.y = hi32(acc0);
        r4.z = lo32(acc1); r4.w = hi32(acc1);
        *(float4*)(out + ((size_t)(b * C + chbase + ch)) * HW + R0 * IMG_W + X0) = r4;
    }
}

// ---------------------------------------------------------------------------
extern "C" void kernel_launch(void* const* d_in, const int* in_sizes, int n_in,
                              void* d_out, int out_size) {
    const float* x   = (const float*)d_in[0];
    const float* wr  = (const float*)d_in[1];
    const float* br  = (const float*)d_in[2];
    const float* wsp = (const float*)d_in[3];
    const float* bs  = (const float*)d_in[4];
    float* out = (float*)d_out;

    static int once = 0;
    if (!once) {
        cudaFuncSetAttribute(k_gemm, cudaFuncAttributeMaxDynamicSharedMemorySize, SM_TOTAL);
        once = 1;
    }
    k_gemm<<<BB * (HW / 128), 256, SM_TOTAL>>>(x, wr, br, wsp, bs);
    dim3 g3(8, G, BB);
    k_invol<<<g3, 256>>>(x, out);
}

// round 15
// speedup vs baseline: 1.0010x; 1.0010x over previous
#include <cuda_runtime.h>
#include <cuda_fp16.h>
#include <cstdint>

#define BB 8
#define C 256
#define G 16
#define KK 9
#define GKK 144
#define HW 4096
#define IMG_W 64
#define IMG_H 64

typedef unsigned long long u64;
typedef unsigned int u32;

__device__ __align__(16) __half g_kmaph[BB * GKK * HW];   // 9.4 MB fp16 scratch

// ---------- scalar helpers ----------
__device__ __forceinline__ u64 ffma2(u64 a, u64 b, u64 c) {
    u64 d; asm("fma.rn.f32x2 %0, %1, %2, %3;" : "=l"(d) : "l"(a), "l"(b), "l"(c)); return d;
}
__device__ __forceinline__ u64 pk(float lo, float hi) {
    u64 r; asm("mov.b64 %0, {%1, %2};" : "=l"(r) : "f"(lo), "f"(hi)); return r;
}
__device__ __forceinline__ float lo32(u64 v) { return __uint_as_float((u32)v); }
__device__ __forceinline__ float hi32(u64 v) { return __uint_as_float((u32)(v >> 32)); }

__device__ __forceinline__ u32 h2u(__half2 h) { u32 r; memcpy(&r, &h, 4); return r; }
__device__ __forceinline__ void split2h(float v0, float v1, u32& h2, u32& l2) {
    __half2 h = __floats2half2_rn(v0, v1);
    h2 = h2u(h);
    l2 = h2u(__floats2half2_rn(v0 - __low2float(h), v1 - __high2float(h)));
}
__device__ __forceinline__ void cvt4h(float4 v, u64& h, u64& l) {
    u32 h0, l0, h1, l1;
    split2h(v.x, v.y, h0, l0);
    split2h(v.z, v.w, h1, l1);
    h = (u64)h0 | ((u64)h1 << 32);
    l = (u64)l0 | ((u64)l1 << 32);
}
__device__ __forceinline__ u64 cvt4h1(float4 v) {
    u32 a = h2u(__floats2half2_rn(v.x, v.y));
    u32 b = h2u(__floats2half2_rn(v.z, v.w));
    return (u64)a | ((u64)b << 32);
}
__device__ __forceinline__ u32 smem_u32(const void* p) {
    u32 a; asm("{ .reg .u64 t; cvta.to.shared.u64 t, %1; cvt.u32.u64 %0, t; }" : "=r"(a) : "l"(p));
    return a;
}

#define MMA(d, a, b0, b1) \
    asm volatile("mma.sync.aligned.m16n8k16.row.col.f32.f16.f16.f32 " \
        "{%0,%1,%2,%3}, {%4,%5,%6,%7}, {%8,%9}, {%0,%1,%2,%3};" \
        : "+f"((d)[0]), "+f"((d)[1]), "+f"((d)[2]), "+f"((d)[3]) \
        : "r"((a)[0]), "r"((a)[1]), "r"((a)[2]), "r"((a)[3]), "r"(b0), "r"(b1))

#define LDSM4T(r, addr) \
    asm volatile("ldmatrix.sync.aligned.m8n8.x4.trans.shared.b16 {%0,%1,%2,%3}, [%4];" \
        : "=r"((r)[0]), "=r"((r)[1]), "=r"((r)[2]), "=r"((r)[3]) : "r"(addr))

#define LDSM4(r, addr) \
    asm volatile("ldmatrix.sync.aligned.m8n8.x4.shared.b16 {%0,%1,%2,%3}, [%4];" \
        : "=r"((r)[0]), "=r"((r)[1]), "=r"((r)[2]), "=r"((r)[3]) : "r"(addr))

// smem byte layout (k_gemm); region [0,43008) reused for kmap staging
#define OFF_XH   0
#define OFF_XL   16384
#define OFF_W1H  32768
#define OFF_WSPH 43008
#define SM_TOTAL 63744
#define KROW 272

__global__ void k_sep() {}   // diagnostic separator so ncu #5 == k_gemm

// ---------------------------------------------------------------------------
// k_gemm: stage1 fp16 2-product HMMA; stage2 single-product (hid fp16).
// kmap staged to smem fp16, coalesced STG.128 out.
// ---------------------------------------------------------------------------
__global__ __launch_bounds__(256, 2)
void k_gemm(const float* __restrict__ x, const float* __restrict__ wr,
            const float* __restrict__ br, const float* __restrict__ wsp,
            const float* __restrict__ bs) {
    extern __shared__ __align__(16) char smem[];
    const int tid = threadIdx.x, wid = tid >> 5, lane = tid & 31;
    const int b = blockIdx.x >> 5, pt = (blockIdx.x & 31) << 7;
    const u32 sbase = smem_u32(smem);

#pragma unroll
    for (int i = 0; i < 9; i++) {
        int f4 = tid + i * 256;
        float4 v = *(const float4*)(wsp + f4 * 4);
        int n = f4 >> 4, kc = (f4 & 15) * 4;
        *(u64*)(smem + OFF_WSPH + n * 144 + kc * 2) = cvt4h1(v);
    }
    {
        const int c = tid >> 3, pxb = (tid & 7) * 16;
        const float* xsrc = x + ((size_t)(b * C + c)) * HW + pt + pxb;
        const int csw = (c & 7) << 3;
#pragma unroll
        for (int q = 0; q < 4; q++) {
            float4 v = *(const float4*)(xsrc + q * 4);
            int col = (pxb + q * 4) ^ csw;
            u64 h, l;
            cvt4h(v, h, l);
            *(u64*)(smem + OFF_XH + c * 256 + col * 2) = h;
            *(u64*)(smem + OFF_XL + c * 256 + col * 2) = l;
        }
        const int n = tid >> 2, koff = (tid & 3) * 8;
#pragma unroll
        for (int q = 0; q < 2; q++) {
            float4 v = *(const float4*)(wr + n * C + koff + q * 4);
            *(u64*)(smem + OFF_W1H + n * 80 + (koff + q * 4) * 2) = cvt4h1(v);
        }
    }
    __syncthreads();

    float acc1[8][4];
#pragma unroll
    for (int j = 0; j < 8; j++)
#pragma unroll
        for (int q = 0; q < 4; q++) acc1[j][q] = 0.f;

    const int m0 = wid * 16;
    const int grp = lane >> 3, li = lane & 7;
    const int krow_off = ((grp & 2) << 2) + li;
    const int coladd = (grp & 1) << 3;
    const int brow = ((lane >> 4) << 3) + li;
    const int bkadd = (grp & 1) << 3;

#pragma unroll 1
    for (int ck = 0; ck < 8; ck++) {
        const int cur = ck & 1, nxt = cur ^ 1;
        float4 xr[4], wrr[2];
        if (ck < 7) {
            const int c = tid >> 3, pxb = (tid & 7) * 16;
            const float* xsrc = x + ((size_t)(b * C + (ck + 1) * 32 + c)) * HW + pt + pxb;
#pragma unroll
            for (int q = 0; q < 4; q++) xr[q] = *(const float4*)(xsrc + q * 4);
            const int n = tid >> 2, koff = (tid & 3) * 8;
#pragma unroll
            for (int q = 0; q < 2; q++)
                wrr[q] = *(const float4*)(wr + n * C + (ck + 1) * 32 + koff + q * 4);
        }
        const u32 sxh = sbase + OFF_XH + cur * 8192;
        const u32 sw1h = sbase + OFF_W1H + cur * 5120;

#pragma unroll
        for (int ks = 0; ks < 2; ks++) {
            const int kb = ks * 16;
            u32 AH[4], AL[4];
            {
                int col = (m0 + coladd) ^ (li << 3);
                u32 ah = sxh + (u32)((kb + krow_off) * 256 + col * 2);
                LDSM4T(AH, ah);
                LDSM4T(AL, ah + 16384);
            }
#pragma unroll
            for (int nj2 = 0; nj2 < 4; nj2++) {
                u32 boff = (u32)((nj2 * 16 + brow) * 80 + (kb + bkadd) * 2);
                u32 BH[4];
                LDSM4(BH, sw1h + boff);
                MMA(acc1[2 * nj2], AH, BH[0], BH[1]);
                MMA(acc1[2 * nj2], AL, BH[0], BH[1]);
                MMA(acc1[2 * nj2 + 1], AH, BH[2], BH[3]);
                MMA(acc1[2 * nj2 + 1], AL, BH[2], BH[3]);
            }
        }
        if (ck < 7) {
            const int c = tid >> 3, pxb = (tid & 7) * 16;
            const int csw = (c & 7) << 3;
#pragma unroll
            for (int q = 0; q < 4; q++) {
                int col = (pxb + q * 4) ^ csw;
                u64 h, l;
                cvt4h(xr[q], h, l);
                *(u64*)(smem + OFF_XH + nxt * 8192 + c * 256 + col * 2) = h;
                *(u64*)(smem + OFF_XL + nxt * 8192 + c * 256 + col * 2) = l;
            }
            const int n = tid >> 2, koff = (tid & 3) * 8;
#pragma unroll
            for (int q = 0; q < 2; q++)
                *(u64*)(smem + OFF_W1H + nxt * 5120 + n * 80 + (koff + q * 4) * 2) = cvt4h1(wrr[q]);
        }
        __syncthreads();
    }

    // ---- in-register: bias+relu -> stage-2 A fragments (single fp16 plane) ----
    u32 A2H[4][4];
#pragma unroll
    for (int ks = 0; ks < 4; ks++) {
        int o0 = ks * 16 + (lane & 3) * 2;
        float b0 = __ldg(br + o0),     b1 = __ldg(br + o0 + 1);
        float b8 = __ldg(br + o0 + 8), b9 = __ldg(br + o0 + 9);
        const float* t0 = acc1[2 * ks];
        const float* t1 = acc1[2 * ks + 1];
        A2H[ks][0] = h2u(__floats2half2_rn(fmaxf(t0[0] + b0, 0.f), fmaxf(t0[1] + b1, 0.f)));
        A2H[ks][1] = h2u(__floats2half2_rn(fmaxf(t0[2] + b0, 0.f), fmaxf(t0[3] + b1, 0.f)));
        A2H[ks][2] = h2u(__floats2half2_rn(fmaxf(t1[0] + b8, 0.f), fmaxf(t1[1] + b9, 0.f)));
        A2H[ks][3] = h2u(__floats2half2_rn(fmaxf(t1[2] + b8, 0.f), fmaxf(t1[3] + b9, 0.f)));
    }

    // ---- stage 2: single-product MMA + stage kmap (fp16) into smem ----
    const u32 swsph = sbase + OFF_WSPH;
    const int pxl = wid * 16 + (lane >> 2);
#pragma unroll 1
    for (int nj2 = 0; nj2 < 9; nj2++) {
        float a2e[4] = {0.f, 0.f, 0.f, 0.f};
        float a2o[4] = {0.f, 0.f, 0.f, 0.f};
#pragma unroll
        for (int ks = 0; ks < 4; ks++) {
            u32 boff = (u32)((nj2 * 16 + brow) * 144 + (ks * 16 + bkadd) * 2);
            u32 BH[4];
            LDSM4(BH, swsph + boff);
            MMA(a2e, A2H[ks], BH[0], BH[1]);
            MMA(a2o, A2H[ks], BH[2], BH[3]);
        }
#pragma unroll
        for (int half = 0; half < 2; half++) {
            const float* a2 = half ? a2o : a2e;
            int o0 = (nj2 * 2 + half) * 8 + (lane & 3) * 2;
            float c0 = __ldg(bs + o0), c1 = __ldg(bs + o0 + 1);
            *(__half*)(smem + o0 * KROW + pxl * 2)             = __float2half_rn(a2[0] + c0);
            *(__half*)(smem + (o0 + 1) * KROW + pxl * 2)       = __float2half_rn(a2[1] + c1);
            *(__half*)(smem + o0 * KROW + (pxl + 8) * 2)       = __float2half_rn(a2[2] + c0);
            *(__half*)(smem + (o0 + 1) * KROW + (pxl + 8) * 2) = __float2half_rn(a2[3] + c1);
        }
    }
    __syncthreads();

#pragma unroll
    for (int j = 0; j < 9; j++) {
        int lin = tid + j * 256;
        int o = lin >> 4, seg = lin & 15;
        uint4 v = *(const uint4*)(smem + o * KROW + seg * 16);
        *(uint4*)(&g_kmaph[((size_t)(b * GKK + o)) * HW + pt + seg * 8]) = v;
    }
}

// ---------------------------------------------------------------------------
// k_invol: planar smem + shuffle halo; kmap fp16 (unchanged from R14).
// ---------------------------------------------------------------------------
__global__ __launch_bounds__(256, 4) void k_invol(const float* __restrict__ x,
                                                  float* __restrict__ out) {
    __shared__ __align__(16) float sm[16 * 10 * 64];
    const int tid = threadIdx.x, strip = blockIdx.x, g = blockIdx.y, b = blockIdx.z;
    const int chbase = g * 16;
    const int cph = tid >> 7;
    const int rr  = (tid >> 4) & 7;
    const int t4  = tid & 15;
    const int R0  = strip * 8 + rr, X0 = t4 * 4;

    const __half* kb = g_kmaph + ((size_t)(b * G + g)) * KK * HW + R0 * IMG_W + X0;
    u64 kraw[9];
#pragma unroll
    for (int k = 0; k < 9; k++) kraw[k] = *(const u64*)(kb + (size_t)k * HW);

#pragma unroll
    for (int it = 0; it < 10; it++) {
        int lin = tid + it * 256;
        int ch = lin / 160;
        int rem = lin - ch * 160;
        int r = rem >> 4, c4 = rem & 15;
        int R = strip * 8 + r - 1;
        float4 v = make_float4(0.f, 0.f, 0.f, 0.f);
        if ((unsigned)R < (unsigned)IMG_H)
            v = *(const float4*)(x + ((size_t)(b * C + chbase + ch)) * HW + R * IMG_W + c4 * 4);
        *(float4*)&sm[ch * 640 + r * 64 + c4 * 4] = v;
    }

    u64 kxy[9], kzw[9];
#pragma unroll
    for (int k = 0; k < 9; k++) {
        u32 plo = (u32)kraw[k], phi = (u32)(kraw[k] >> 32);
        float2 f01 = __half22float2(*(__half2*)&plo);
        float2 f23 = __half22float2(*(__half2*)&phi);
        kxy[k] = pk(f01.x, f01.y);
        kzw[k] = pk(f23.x, f23.y);
    }
    __syncthreads();

#pragma unroll
    for (int ci = 0; ci < 8; ci++) {
        const int ch = cph * 8 + ci;
        const float* pl = &sm[ch * 640 + rr * 64 + X0];
        u64 acc0 = 0ull, acc1 = 0ull;
#pragma unroll
        for (int dy = 0; dy < 3; dy++) {
            ulonglong2 q = *(const ulonglong2*)(pl + dy * 64);
            float a0 = lo32(q.x), a1 = hi32(q.x), a2 = lo32(q.y), a3 = hi32(q.y);
            float s  = __shfl_up_sync(0xFFFFFFFFu, a3, 1, 16);
            float b0 = __shfl_down_sync(0xFFFFFFFFu, a0, 1, 16);
            if (t4 == 0)  s  = 0.f;
            if (t4 == 15) b0 = 0.f;
            u64 pm  = pk(s,  a0);
            u64 p12 = pk(a1, a2);
            u64 p34 = pk(a3, b0);
            acc0 = ffma2(pm,  kxy[dy * 3 + 0], acc0);
            acc0 = ffma2(q.x, kxy[dy * 3 + 1], acc0);
            acc0 = ffma2(p12, kxy[dy * 3 + 2], acc0);
            acc1 = ffma2(p12, kzw[dy * 3 + 0], acc1);
            acc1 = ffma2(q.y, kzw[dy * 3 + 1], acc1);
            acc1 = ffma2(p34, kzw[dy * 3 + 2], acc1);
        }
        float4 r4;
        r4.x = lo32(acc0); r4.y = hi32(acc0);
        r4.z = lo32(acc1); r4.w = hi32(acc1);
        *(float4*)(out + ((size_t)(b * C + chbase + ch)) * HW + R0 * IMG_W + X0) = r4;
    }
}

// ---------------------------------------------------------------------------
extern "C" void kernel_launch(void* const* d_in, const int* in_sizes, int n_in,
                              void* d_out, int out_size) {
    const float* x   = (const float*)d_in[0];
    const float* wr  = (const float*)d_in[1];
    const float* br  = (const float*)d_in[2];
    const float* wsp = (const float*)d_in[3];
    const float* bs  = (const float*)d_in[4];
    float* out = (float*)d_out;

    static int once = 0;
    if (!once) {
        cudaFuncSetAttribute(k_gemm, cudaFuncAttributeMaxDynamicSharedMemorySize, SM_TOTAL);
        once = 1;
    }
    // pattern (gemm, sep, invol): stream pos 5 = k_gemm for ncu -s 5
    k_gemm<<<BB * (HW / 128), 256, SM_TOTAL>>>(x, wr, br, wsp, bs);
    k_sep<<<1, 32>>>();
    dim3 g3(8, G, BB);
    k_invol<<<g3, 256>>>(x, out);
}

// round 16
// speedup vs baseline: 1.0656x; 1.0645x over previous
#include <cuda_runtime.h>
#include <cuda_fp16.h>
#include <cstdint>

#define BB 8
#define C 256
#define G 16
#define KK 9
#define GKK 144
#define HW 4096
#define IMG_W 64
#define IMG_H 64

typedef unsigned long long u64;
typedef unsigned int u32;

__device__ __align__(16) __half g_kmaph[BB * GKK * HW];   // 9.4 MB fp16 scratch

// ---------- scalar helpers ----------
__device__ __forceinline__ u64 ffma2(u64 a, u64 b, u64 c) {
    u64 d; asm("fma.rn.f32x2 %0, %1, %2, %3;" : "=l"(d) : "l"(a), "l"(b), "l"(c)); return d;
}
__device__ __forceinline__ u64 pk(float lo, float hi) {
    u64 r; asm("mov.b64 %0, {%1, %2};" : "=l"(r) : "f"(lo), "f"(hi)); return r;
}
__device__ __forceinline__ float lo32(u64 v) { return __uint_as_float((u32)v); }
__device__ __forceinline__ float hi32(u64 v) { return __uint_as_float((u32)(v >> 32)); }

__device__ __forceinline__ u32 h2u(__half2 h) { u32 r; memcpy(&r, &h, 4); return r; }
__device__ __forceinline__ u64 cvt4h1(float4 v) {
    u32 a = h2u(__floats2half2_rn(v.x, v.y));
    u32 b = h2u(__floats2half2_rn(v.z, v.w));
    return (u64)a | ((u64)b << 32);
}
__device__ __forceinline__ u32 smem_u32(const void* p) {
    u32 a; asm("{ .reg .u64 t; cvta.to.shared.u64 t, %1; cvt.u32.u64 %0, t; }" : "=r"(a) : "l"(p));
    return a;
}

#define MMA(d, a, b0, b1) \
    asm volatile("mma.sync.aligned.m16n8k16.row.col.f32.f16.f16.f32 " \
        "{%0,%1,%2,%3}, {%4,%5,%6,%7}, {%8,%9}, {%0,%1,%2,%3};" \
        : "+f"((d)[0]), "+f"((d)[1]), "+f"((d)[2]), "+f"((d)[3]) \
        : "r"((a)[0]), "r"((a)[1]), "r"((a)[2]), "r"((a)[3]), "r"(b0), "r"(b1))

#define LDSM4T(r, addr) \
    asm volatile("ldmatrix.sync.aligned.m8n8.x4.trans.shared.b16 {%0,%1,%2,%3}, [%4];" \
        : "=r"((r)[0]), "=r"((r)[1]), "=r"((r)[2]), "=r"((r)[3]) : "r"(addr))

#define LDSM4(r, addr) \
    asm volatile("ldmatrix.sync.aligned.m8n8.x4.shared.b16 {%0,%1,%2,%3}, [%4];" \
        : "=r"((r)[0]), "=r"((r)[1]), "=r"((r)[2]), "=r"((r)[3]) : "r"(addr))

// smem byte layout; region [0,39168) reused for kmap staging
#define OFF_XH   0        // 2 bufs x [32 k][128 px] fp16 (256B rows) = 16384
#define OFF_W1H  16384    // 2 bufs x [64 n][40 k] fp16 (80B rows) = 10240
#define OFF_WSPH 26624    // [144 n][72 k] fp16 (144B rows) = 20736
#define SM_TOTAL 47360
#define KROW 272

// ---------------------------------------------------------------------------
// k_gemm: single-product fp16 HMMA for both stages (x, hid, weights, kmap all
// fp16 single-plane). kmap staged to smem, coalesced STG.128 out.
// ---------------------------------------------------------------------------
__global__ __launch_bounds__(256, 2)
void k_gemm(const float* __restrict__ x, const float* __restrict__ wr,
            const float* __restrict__ br, const float* __restrict__ wsp,
            const float* __restrict__ bs) {
    extern __shared__ __align__(16) char smem[];
    const int tid = threadIdx.x, wid = tid >> 5, lane = tid & 31;
    const int b = blockIdx.x >> 5, pt = (blockIdx.x & 31) << 7;
    const u32 sbase = smem_u32(smem);

#pragma unroll
    for (int i = 0; i < 9; i++) {
        int f4 = tid + i * 256;
        float4 v = *(const float4*)(wsp + f4 * 4);
        int n = f4 >> 4, kc = (f4 & 15) * 4;
        *(u64*)(smem + OFF_WSPH + n * 144 + kc * 2) = cvt4h1(v);
    }
    {
        const int c = tid >> 3, pxb = (tid & 7) * 16;
        const float* xsrc = x + ((size_t)(b * C + c)) * HW + pt + pxb;
        const int csw = (c & 7) << 3;
#pragma unroll
        for (int q = 0; q < 4; q++) {
            float4 v = *(const float4*)(xsrc + q * 4);
            int col = (pxb + q * 4) ^ csw;
            *(u64*)(smem + OFF_XH + c * 256 + col * 2) = cvt4h1(v);
        }
        const int n = tid >> 2, koff = (tid & 3) * 8;
#pragma unroll
        for (int q = 0; q < 2; q++) {
            float4 v = *(const float4*)(wr + n * C + koff + q * 4);
            *(u64*)(smem + OFF_W1H + n * 80 + (koff + q * 4) * 2) = cvt4h1(v);
        }
    }
    __syncthreads();

    float acc1[8][4];
#pragma unroll
    for (int j = 0; j < 8; j++)
#pragma unroll
        for (int q = 0; q < 4; q++) acc1[j][q] = 0.f;

    const int m0 = wid * 16;
    const int grp = lane >> 3, li = lane & 7;
    const int krow_off = ((grp & 2) << 2) + li;
    const int coladd = (grp & 1) << 3;
    const int brow = ((lane >> 4) << 3) + li;
    const int bkadd = (grp & 1) << 3;

#pragma unroll 1
    for (int ck = 0; ck < 8; ck++) {
        const int cur = ck & 1, nxt = cur ^ 1;
        float4 xr[4], wrr[2];
        if (ck < 7) {
            const int c = tid >> 3, pxb = (tid & 7) * 16;
            const float* xsrc = x + ((size_t)(b * C + (ck + 1) * 32 + c)) * HW + pt + pxb;
#pragma unroll
            for (int q = 0; q < 4; q++) xr[q] = *(const float4*)(xsrc + q * 4);
            const int n = tid >> 2, koff = (tid & 3) * 8;
#pragma unroll
            for (int q = 0; q < 2; q++)
                wrr[q] = *(const float4*)(wr + n * C + (ck + 1) * 32 + koff + q * 4);
        }
        const u32 sxh = sbase + OFF_XH + cur * 8192;
        const u32 sw1h = sbase + OFF_W1H + cur * 5120;

#pragma unroll
        for (int ks = 0; ks < 2; ks++) {
            const int kb = ks * 16;
            u32 AH[4];
            {
                int col = (m0 + coladd) ^ (li << 3);
                LDSM4T(AH, sxh + (u32)((kb + krow_off) * 256 + col * 2));
            }
#pragma unroll
            for (int nj2 = 0; nj2 < 4; nj2++) {
                u32 boff = (u32)((nj2 * 16 + brow) * 80 + (kb + bkadd) * 2);
                u32 BH[4];
                LDSM4(BH, sw1h + boff);
                MMA(acc1[2 * nj2],     AH, BH[0], BH[1]);
                MMA(acc1[2 * nj2 + 1], AH, BH[2], BH[3]);
            }
        }
        if (ck < 7) {
            const int c = tid >> 3, pxb = (tid & 7) * 16;
            const int csw = (c & 7) << 3;
#pragma unroll
            for (int q = 0; q < 4; q++) {
                int col = (pxb + q * 4) ^ csw;
                *(u64*)(smem + OFF_XH + nxt * 8192 + c * 256 + col * 2) = cvt4h1(xr[q]);
            }
            const int n = tid >> 2, koff = (tid & 3) * 8;
#pragma unroll
            for (int q = 0; q < 2; q++)
                *(u64*)(smem + OFF_W1H + nxt * 5120 + n * 80 + (koff + q * 4) * 2) = cvt4h1(wrr[q]);
        }
        __syncthreads();
    }

    // ---- in-register: bias+relu -> stage-2 A fragments (fp16) ----
    u32 A2H[4][4];
#pragma unroll
    for (int ks = 0; ks < 4; ks++) {
        int o0 = ks * 16 + (lane & 3) * 2;
        float b0 = __ldg(br + o0),     b1 = __ldg(br + o0 + 1);
        float b8 = __ldg(br + o0 + 8), b9 = __ldg(br + o0 + 9);
        const float* t0 = acc1[2 * ks];
        const float* t1 = acc1[2 * ks + 1];
        A2H[ks][0] = h2u(__floats2half2_rn(fmaxf(t0[0] + b0, 0.f), fmaxf(t0[1] + b1, 0.f)));
        A2H[ks][1] = h2u(__floats2half2_rn(fmaxf(t0[2] + b0, 0.f), fmaxf(t0[3] + b1, 0.f)));
        A2H[ks][2] = h2u(__floats2half2_rn(fmaxf(t1[0] + b8, 0.f), fmaxf(t1[1] + b9, 0.f)));
        A2H[ks][3] = h2u(__floats2half2_rn(fmaxf(t1[2] + b8, 0.f), fmaxf(t1[3] + b9, 0.f)));
    }

    // ---- stage 2: single-product MMA + stage kmap (fp16) into smem ----
    const u32 swsph = sbase + OFF_WSPH;
    const int pxl = wid * 16 + (lane >> 2);
#pragma unroll 1
    for (int nj2 = 0; nj2 < 9; nj2++) {
        float a2e[4] = {0.f, 0.f, 0.f, 0.f};
        float a2o[4] = {0.f, 0.f, 0.f, 0.f};
#pragma unroll
        for (int ks = 0; ks < 4; ks++) {
            u32 boff = (u32)((nj2 * 16 + brow) * 144 + (ks * 16 + bkadd) * 2);
            u32 BH[4];
            LDSM4(BH, swsph + boff);
            MMA(a2e, A2H[ks], BH[0], BH[1]);
            MMA(a2o, A2H[ks], BH[2], BH[3]);
        }
#pragma unroll
        for (int half = 0; half < 2; half++) {
            const float* a2 = half ? a2o : a2e;
            int o0 = (nj2 * 2 + half) * 8 + (lane & 3) * 2;
            float c0 = __ldg(bs + o0), c1 = __ldg(bs + o0 + 1);
            *(__half*)(smem + o0 * KROW + pxl * 2)             = __float2half_rn(a2[0] + c0);
            *(__half*)(smem + (o0 + 1) * KROW + pxl * 2)       = __float2half_rn(a2[1] + c1);
            *(__half*)(smem + o0 * KROW + (pxl + 8) * 2)       = __float2half_rn(a2[2] + c0);
            *(__half*)(smem + (o0 + 1) * KROW + (pxl + 8) * 2) = __float2half_rn(a2[3] + c1);
        }
    }
    __syncthreads();

#pragma unroll
    for (int j = 0; j < 9; j++) {
        int lin = tid + j * 256;
        int o = lin >> 4, seg = lin & 15;
        uint4 v = *(const uint4*)(smem + o * KROW + seg * 16);
        *(uint4*)(&g_kmaph[((size_t)(b * GKK + o)) * HW + pt + seg * 8]) = v;
    }
}

// ---------------------------------------------------------------------------
// k_invol: planar smem + shuffle halo; kmap fp16 (unchanged from R14/R15).
// ---------------------------------------------------------------------------
__global__ __launch_bounds__(256, 4) void k_invol(const float* __restrict__ x,
                                                  float* __restrict__ out) {
    __shared__ __align__(16) float sm[16 * 10 * 64];
    const int tid = threadIdx.x, strip = blockIdx.x, g = blockIdx.y, b = blockIdx.z;
    const int chbase = g * 16;
    const int cph = tid >> 7;
    const int rr  = (tid >> 4) & 7;
    const int t4  = tid & 15;
    const int R0  = strip * 8 + rr, X0 = t4 * 4;

    const __half* kb = g_kmaph + ((size_t)(b * G + g)) * KK * HW + R0 * IMG_W + X0;
    u64 kraw[9];
#pragma unroll
    for (int k = 0; k < 9; k++) kraw[k] = *(const u64*)(kb + (size_t)k * HW);

#pragma unroll
    for (int it = 0; it < 10; it++) {
        int lin = tid + it * 256;
        int ch = lin / 160;
        int rem = lin - ch * 160;
        int r = rem >> 4, c4 = rem & 15;
        int R = strip * 8 + r - 1;
        float4 v = make_float4(0.f, 0.f, 0.f, 0.f);
        if ((unsigned)R < (unsigned)IMG_H)
            v = *(const float4*)(x + ((size_t)(b * C + chbase + ch)) * HW + R * IMG_W + c4 * 4);
        *(float4*)&sm[ch * 640 + r * 64 + c4 * 4] = v;
    }

    u64 kxy[9], kzw[9];
#pragma unroll
    for (int k = 0; k < 9; k++) {
        u32 plo = (u32)kraw[k], phi = (u32)(kraw[k] >> 32);
        float2 f01 = __half22float2(*(__half2*)&plo);
        float2 f23 = __half22float2(*(__half2*)&phi);
        kxy[k] = pk(f01.x, f01.y);
        kzw[k] = pk(f23.x, f23.y);
    }
    __syncthreads();

#pragma unroll
    for (int ci = 0; ci < 8; ci++) {
        const int ch = cph * 8 + ci;
        const float* pl = &sm[ch * 640 + rr * 64 + X0];
        u64 acc0 = 0ull, acc1 = 0ull;
#pragma unroll
        for (int dy = 0; dy < 3; dy++) {
            ulonglong2 q = *(const ulonglong2*)(pl + dy * 64);
            float a0 = lo32(q.x), a1 = hi32(q.x), a2 = lo32(q.y), a3 = hi32(q.y);
            float s  = __shfl_up_sync(0xFFFFFFFFu, a3, 1, 16);
            float b0 = __shfl_down_sync(0xFFFFFFFFu, a0, 1, 16);
            if (t4 == 0)  s  = 0.f;
            if (t4 == 15) b0 = 0.f;
            u64 pm  = pk(s,  a0);
            u64 p12 = pk(a1, a2);
            u64 p34 = pk(a3, b0);
            acc0 = ffma2(pm,  kxy[dy * 3 + 0], acc0);
            acc0 = ffma2(q.x, kxy[dy * 3 + 1], acc0);
            acc0 = ffma2(p12, kxy[dy * 3 + 2], acc0);
            acc1 = ffma2(p12, kzw[dy * 3 + 0], acc1);
            acc1 = ffma2(q.y, kzw[dy * 3 + 1], acc1);
            acc1 = ffma2(p34, kzw[dy * 3 + 2], acc1);
        }
        float4 r4;
        r4.x = lo32(acc0); r4.y = hi32(acc0);
        r4.z = lo32(acc1); r4.w = hi32(acc1);
        *(float4*)(out + ((size_t)(b * C + chbase + ch)) * HW + R0 * IMG_W + X0) = r4;
    }
}

// ---------------------------------------------------------------------------
extern "C" void kernel_launch(void* const* d_in, const int* in_sizes, int n_in,
                              void* d_out, int out_size) {
    const float* x   = (const float*)d_in[0];
    const float* wr  = (const float*)d_in[1];
    const float* br  = (const float*)d_in[2];
    const float* wsp = (const float*)d_in[3];
    const float* bs  = (const float*)d_in[4];
    float* out = (float*)d_out;

    static int once = 0;
    if (!once) {
        cudaFuncSetAttribute(k_gemm, cudaFuncAttributeMaxDynamicSharedMemorySize, SM_TOTAL);
        once = 1;
    }
    k_gemm<<<BB * (HW / 128), 256, SM_TOTAL>>>(x, wr, br, wsp, bs);
    dim3 g3(8, G, BB);
    k_invol<<<g3, 256>>>(x, out);
}

// round 17
// speedup vs baseline: 1.1416x; 1.0714x over previous
#include <cuda_runtime.h>
#include <cuda_fp16.h>
#include <cstdint>

#define BB 8
#define C 256
#define G 16
#define KK 9
#define GKK 144
#define HW 4096
#define IMG_W 64
#define IMG_H 64

typedef unsigned long long u64;
typedef unsigned int u32;

__device__ __align__(16) __half g_kmaph[BB * GKK * HW];   // 9.4 MB fp16 scratch

// ---------- scalar helpers ----------
__device__ __forceinline__ u64 ffma2(u64 a, u64 b, u64 c) {
    u64 d; asm("fma.rn.f32x2 %0, %1, %2, %3;" : "=l"(d) : "l"(a), "l"(b), "l"(c)); return d;
}
__device__ __forceinline__ u64 pk(float lo, float hi) {
    u64 r; asm("mov.b64 %0, {%1, %2};" : "=l"(r) : "f"(lo), "f"(hi)); return r;
}
__device__ __forceinline__ float lo32(u64 v) { return __uint_as_float((u32)v); }
__device__ __forceinline__ float hi32(u64 v) { return __uint_as_float((u32)(v >> 32)); }

__device__ __forceinline__ u32 h2u(__half2 h) { u32 r; memcpy(&r, &h, 4); return r; }
__device__ __forceinline__ u64 cvt4h1(float4 v) {
    u32 a = h2u(__floats2half2_rn(v.x, v.y));
    u32 b = h2u(__floats2half2_rn(v.z, v.w));
    return (u64)a | ((u64)b << 32);
}
__device__ __forceinline__ u32 smem_u32(const void* p) {
    u32 a; asm("{ .reg .u64 t; cvta.to.shared.u64 t, %1; cvt.u32.u64 %0, t; }" : "=r"(a) : "l"(p));
    return a;
}

#define MMA(d, a, b0, b1) \
    asm volatile("mma.sync.aligned.m16n8k16.row.col.f32.f16.f16.f32 " \
        "{%0,%1,%2,%3}, {%4,%5,%6,%7}, {%8,%9}, {%0,%1,%2,%3};" \
        : "+f"((d)[0]), "+f"((d)[1]), "+f"((d)[2]), "+f"((d)[3]) \
        : "r"((a)[0]), "r"((a)[1]), "r"((a)[2]), "r"((a)[3]), "r"(b0), "r"(b1))

#define LDSM4(r, addr) \
    asm volatile("ldmatrix.sync.aligned.m8n8.x4.shared.b16 {%0,%1,%2,%3}, [%4];" \
        : "=r"((r)[0]), "=r"((r)[1]), "=r"((r)[2]), "=r"((r)[3]) : "r"(addr))

// smem byte layout:
//   [0, 39168)      kmap staging (stage-2 epilogue)  -- overlaps W1
//   [0, 33792)      W1: 64 n-rows x 264 halfs (528B stride), dead after stage 1
//   [39168, 59904)  WSPH: 144 n-rows x 72 halfs (144B stride)
#define OFF_W1   0
#define W1ROW    528
#define OFF_WSPH 39168
#define SM_TOTAL 59904
#define KROW 272

// ---------------------------------------------------------------------------
// k_gemm: barrier-free stage-1. A-fragments loaded straight from gmem x
// (8 LDG.32/lane/k-step via 4 pointers), weights preloaded once in smem.
// Stage 2 (N=144) + fp16 kmap staging + coalesced store unchanged.
// ---------------------------------------------------------------------------
__global__ __launch_bounds__(256, 2)
void k_gemm(const float* __restrict__ x, const float* __restrict__ wr,
            const float* __restrict__ br, const float* __restrict__ wsp,
            const float* __restrict__ bs) {
    extern __shared__ __align__(16) char smem[];
    const int tid = threadIdx.x, wid = tid >> 5, lane = tid & 31;
    const int b = blockIdx.x >> 5, pt = (blockIdx.x & 31) << 7;
    const u32 sbase = smem_u32(smem);

    // ---- one-time weight preload ----
#pragma unroll
    for (int i = 0; i < 16; i++) {                 // w1: 4096 float4
        int f4 = tid + i * 256;
        int n = f4 >> 6, kc = (f4 & 63) * 4;
        float4 v = *(const float4*)(wr + f4 * 4);  // wr row-major [64][256]
        *(u64*)(smem + OFF_W1 + n * W1ROW + kc * 2) = cvt4h1(v);
    }
#pragma unroll
    for (int i = 0; i < 9; i++) {                  // wsp: 2304 float4
        int f4 = tid + i * 256;
        int n = f4 >> 4, kc = (f4 & 15) * 4;
        float4 v = *(const float4*)(wsp + f4 * 4);
        *(u64*)(smem + OFF_WSPH + n * 144 + kc * 2) = cvt4h1(v);
    }
    __syncthreads();

    float acc1[8][4];
#pragma unroll
    for (int j = 0; j < 8; j++)
#pragma unroll
        for (int q = 0; q < 4; q++) acc1[j][q] = 0.f;

    const int m0 = wid * 16;
    const int grp = lane >> 3, li = lane & 7;
    const int brow = ((lane >> 4) << 3) + li;      // ldmatrix B: n-row
    const int bkadd = (grp & 1) << 3;              // ldmatrix B: k add

    // ---- stage 1: direct gmem A-frags, no barriers ----
    {
        const int c0 = (lane & 3) * 2;
        const float* xb = x + (size_t)b * C * HW + pt + m0 + (lane >> 2);
        const float* p0 = xb + (size_t)(c0) * HW;
        const float* p1 = xb + (size_t)(c0 + 1) * HW;
        const float* p8 = xb + (size_t)(c0 + 8) * HW;
        const float* p9 = xb + (size_t)(c0 + 9) * HW;
        const size_t stp = (size_t)16 * HW;

        float f[8];
        f[0] = p0[0]; f[1] = p1[0]; f[2] = p0[8]; f[3] = p1[8];
        f[4] = p8[0]; f[5] = p9[0]; f[6] = p8[8]; f[7] = p9[8];

#pragma unroll
        for (int k16 = 0; k16 < 16; k16++) {
            float g[8];
            if (k16 < 15) {
                const float* q0 = p0 + (k16 + 1) * stp;
                const float* q1 = p1 + (k16 + 1) * stp;
                const float* q8 = p8 + (k16 + 1) * stp;
                const float* q9 = p9 + (k16 + 1) * stp;
                g[0] = q0[0]; g[1] = q1[0]; g[2] = q0[8]; g[3] = q1[8];
                g[4] = q8[0]; g[5] = q9[0]; g[6] = q8[8]; g[7] = q9[8];
            }
            u32 AH[4];
            AH[0] = h2u(__floats2half2_rn(f[0], f[1]));
            AH[1] = h2u(__floats2half2_rn(f[2], f[3]));
            AH[2] = h2u(__floats2half2_rn(f[4], f[5]));
            AH[3] = h2u(__floats2half2_rn(f[6], f[7]));
#pragma unroll
            for (int nj2 = 0; nj2 < 4; nj2++) {
                u32 boff = (u32)((nj2 * 16 + brow) * W1ROW + (k16 * 16 + bkadd) * 2);
                u32 BH[4];
                LDSM4(BH, sbase + OFF_W1 + boff);
                MMA(acc1[2 * nj2],     AH, BH[0], BH[1]);
                MMA(acc1[2 * nj2 + 1], AH, BH[2], BH[3]);
            }
#pragma unroll
            for (int q = 0; q < 8; q++) f[q] = g[q];
        }
    }

    // ---- in-register: bias+relu -> stage-2 A fragments (fp16) ----
    u32 A2H[4][4];
#pragma unroll
    for (int ks = 0; ks < 4; ks++) {
        int o0 = ks * 16 + (lane & 3) * 2;
        float b0 = __ldg(br + o0),     b1 = __ldg(br + o0 + 1);
        float b8 = __ldg(br + o0 + 8), b9 = __ldg(br + o0 + 9);
        const float* t0 = acc1[2 * ks];
        const float* t1 = acc1[2 * ks + 1];
        A2H[ks][0] = h2u(__floats2half2_rn(fmaxf(t0[0] + b0, 0.f), fmaxf(t0[1] + b1, 0.f)));
        A2H[ks][1] = h2u(__floats2half2_rn(fmaxf(t0[2] + b0, 0.f), fmaxf(t0[3] + b1, 0.f)));
        A2H[ks][2] = h2u(__floats2half2_rn(fmaxf(t1[0] + b8, 0.f), fmaxf(t1[1] + b9, 0.f)));
        A2H[ks][3] = h2u(__floats2half2_rn(fmaxf(t1[2] + b8, 0.f), fmaxf(t1[3] + b9, 0.f)));
    }

    // W1 region is about to be overwritten by kmap staging: wait for ALL warps
    // to finish stage-1 LDSM reads.
    __syncthreads();

    // ---- stage 2: single-product MMA + stage kmap (fp16) into smem ----
    const u32 swsph = sbase + OFF_WSPH;
    const int pxl = wid * 16 + (lane >> 2);
#pragma unroll 1
    for (int nj2 = 0; nj2 < 9; nj2++) {
        float a2e[4] = {0.f, 0.f, 0.f, 0.f};
        float a2o[4] = {0.f, 0.f, 0.f, 0.f};
#pragma unroll
        for (int ks = 0; ks < 4; ks++) {
            u32 boff = (u32)((nj2 * 16 + brow) * 144 + (ks * 16 + bkadd) * 2);
            u32 BH[4];
            LDSM4(BH, swsph + boff);
            MMA(a2e, A2H[ks], BH[0], BH[1]);
            MMA(a2o, A2H[ks], BH[2], BH[3]);
        }
#pragma unroll
        for (int half = 0; half < 2; half++) {
            const float* a2 = half ? a2o : a2e;
            int o0 = (nj2 * 2 + half) * 8 + (lane & 3) * 2;
            float c0 = __ldg(bs + o0), c1 = __ldg(bs + o0 + 1);
            *(__half*)(smem + o0 * KROW + pxl * 2)             = __float2half_rn(a2[0] + c0);
            *(__half*)(smem + (o0 + 1) * KROW + pxl * 2)       = __float2half_rn(a2[1] + c1);
            *(__half*)(smem + o0 * KROW + (pxl + 8) * 2)       = __float2half_rn(a2[2] + c0);
            *(__half*)(smem + (o0 + 1) * KROW + (pxl + 8) * 2) = __float2half_rn(a2[3] + c1);
        }
    }
    __syncthreads();

#pragma unroll
    for (int j = 0; j < 9; j++) {
        int lin = tid + j * 256;
        int o = lin >> 4, seg = lin & 15;
        uint4 v = *(const uint4*)(smem + o * KROW + seg * 16);
        *(uint4*)(&g_kmaph[((size_t)(b * GKK + o)) * HW + pt + seg * 8]) = v;
    }
}

// ---------------------------------------------------------------------------
// k_invol: unchanged from R16 (planar smem + shuffle halo, fp16 kmap).
// ---------------------------------------------------------------------------
__global__ __launch_bounds__(256, 4) void k_invol(const float* __restrict__ x,
                                                  float* __restrict__ out) {
    __shared__ __align__(16) float sm[16 * 10 * 64];
    const int tid = threadIdx.x, strip = blockIdx.x, g = blockIdx.y, b = blockIdx.z;
    const int chbase = g * 16;
    const int cph = tid >> 7;
    const int rr  = (tid >> 4) & 7;
    const int t4  = tid & 15;
    const int R0  = strip * 8 + rr, X0 = t4 * 4;

    const __half* kb = g_kmaph + ((size_t)(b * G + g)) * KK * HW + R0 * IMG_W + X0;
    u64 kraw[9];
#pragma unroll
    for (int k = 0; k < 9; k++) kraw[k] = *(const u64*)(kb + (size_t)k * HW);

#pragma unroll
    for (int it = 0; it < 10; it++) {
        int lin = tid + it * 256;
        int ch = lin / 160;
        int rem = lin - ch * 160;
        int r = rem >> 4, c4 = rem & 15;
        int R = strip * 8 + r - 1;
        float4 v = make_float4(0.f, 0.f, 0.f, 0.f);
        if ((unsigned)R < (unsigned)IMG_H)
            v = *(const float4*)(x + ((size_t)(b * C + chbase + ch)) * HW + R * IMG_W + c4 * 4);
        *(float4*)&sm[ch * 640 + r * 64 + c4 * 4] = v;
    }

    u64 kxy[9], kzw[9];
#pragma unroll
    for (int k = 0; k < 9; k++) {
        u32 plo = (u32)kraw[k], phi = (u32)(kraw[k] >> 32);
        float2 f01 = __half22float2(*(__half2*)&plo);
        float2 f23 = __half22float2(*(__half2*)&phi);
        kxy[k] = pk(f01.x, f01.y);
        kzw[k] = pk(f23.x, f23.y);
    }
    __syncthreads();

#pragma unroll
    for (int ci = 0; ci < 8; ci++) {
        const int ch = cph * 8 + ci;
        const float* pl = &sm[ch * 640 + rr * 64 + X0];
        u64 acc0 = 0ull, acc1 = 0ull;
#pragma unroll
        for (int dy = 0; dy < 3; dy++) {
            ulonglong2 q = *(const ulonglong2*)(pl + dy * 64);
            float a0 = lo32(q.x), a1 = hi32(q.x), a2 = lo32(q.y), a3 = hi32(q.y);
            float s  = __shfl_up_sync(0xFFFFFFFFu, a3, 1, 16);
            float b0 = __shfl_down_sync(0xFFFFFFFFu, a0, 1, 16);
            if (t4 == 0)  s  = 0.f;
            if (t4 == 15) b0 = 0.f;
            u64 pm  = pk(s,  a0);
            u64 p12 = pk(a1, a2);
            u64 p34 = pk(a3, b0);
            acc0 = ffma2(pm,  kxy[dy * 3 + 0], acc0);
            acc0 = ffma2(q.x, kxy[dy * 3 + 1], acc0);
            acc0 = ffma2(p12, kxy[dy * 3 + 2], acc0);
            acc1 = ffma2(p12, kzw[dy * 3 + 0], acc1);
            acc1 = ffma2(q.y, kzw[dy * 3 + 1], acc1);
            acc1 = ffma2(p34, kzw[dy * 3 + 2], acc1);
        }
        float4 r4;
        r4.x = lo32(acc0); r4.y = hi32(acc0);
        r4.z = lo32(acc1); r4.w = hi32(acc1);
        *(float4*)(out + ((size_t)(b * C + chbase + ch)) * HW + R0 * IMG_W + X0) = r4;
    }
}

// ---------------------------------------------------------------------------
extern "C" void kernel_launch(void* const* d_in, const int* in_sizes, int n_in,
                              void* d_out, int out_size) {
    const float* x   = (const float*)d_in[0];
    const float* wr  = (const float*)d_in[1];
    const float* br  = (const float*)d_in[2];
    const float* wsp = (const float*)d_in[3];
    const float* bs  = (const float*)d_in[4];
    float* out = (float*)d_out;

    static int once = 0;
    if (!once) {
        cudaFuncSetAttribute(k_gemm, cudaFuncAttributeMaxDynamicSharedMemorySize, SM_TOTAL);
        once = 1;
    }
    k_gemm<<<BB * (HW / 128), 256, SM_TOTAL>>>(x, wr, br, wsp, bs);
    dim3 g3(8, G, BB);
    k_invol<<<g3, 256>>>(x, out);
}